// round 12
// baseline (speedup 1.0000x reference)
#include <cstdint>
#include <cuda_runtime.h>
#include <cuda_bf16.h>
#include <mma.h>

using namespace nvcuda;

// ---------------- problem constants ----------------
#define L_SEQ   1024
#define D_MODEL 768
#define D_INNER 1536
#define D_STATE 64
#define D_CONV  4
#define DT_RANK 48
#define DBL_N   (DT_RANK + 2*D_STATE)   // 176
#define LN_EPS  1e-5f

#define GEMM_THREADS 256
#define STAGES 3

// chunked scan
#define NSEG 8
#define SEG  (L_SEQ / NSEG)             // 128
#define DN   (D_INNER * D_STATE)        // 98304

// weight sizes
#define N_WIN  (D_MODEL * 2 * D_INNER)
#define N_WX   (D_INNER * DBL_N)
#define N_WDT  (DT_RANK * D_INNER)
#define N_WOUT (D_INNER * D_MODEL)

// ---------------- scratch (no allocations allowed) ----------------
__device__ float g_xn [L_SEQ * D_MODEL];
__device__ float g_xz [L_SEQ * 2 * D_INNER];
__device__ float g_xc [L_SEQ * D_INNER];
__device__ float g_dbl[L_SEQ * DBL_N];
__device__ float g_dblr[L_SEQ * DT_RANK];
__device__ float g_xcT[D_INNER * L_SEQ];
__device__ float g_dtT[D_INNER * L_SEQ];
__device__ float g_zsT[D_INNER * L_SEQ];
__device__ float g_y  [L_SEQ * D_INNER];
__device__ float g_part[8 * L_SEQ * DBL_N > 4 * L_SEQ * D_MODEL ?
                        8 * L_SEQ * DBL_N : 4 * L_SEQ * D_MODEL];
__device__ float g_cumA [NSEG * DN];
__device__ float g_hp   [NSEG * DN];
__device__ float g_hinit[NSEG * DN];
__device__ float g_rWin [N_WIN];
__device__ float g_rWx  [N_WX];
__device__ float g_rWdt [N_WDT];
__device__ float g_rWout[N_WOUT];
__device__ int   g_cnt[512];   // [0,256): GEMM split-K; [256,448): pass1 dblocks

// ---------------- helpers ----------------
__device__ __forceinline__ float to_tf32(float x) {
    float r;
    asm("cvt.rna.tf32.f32 %0, %1;" : "=f"(r) : "f"(x));
    return r;
}
__device__ __forceinline__ void cp_async16(void* smem_dst, const void* gmem_src) {
    unsigned int dst = (unsigned int)__cvta_generic_to_shared(smem_dst);
    asm volatile("cp.async.cg.shared.global [%0], [%1], 16;\n" :: "r"(dst), "l"(gmem_src));
}
__device__ __forceinline__ void cp_async_commit() {
    asm volatile("cp.async.commit_group;\n");
}
template<int N>
__device__ __forceinline__ void cp_async_wait() {
    asm volatile("cp.async.wait_group %0;\n" :: "n"(N));
}

// ---------------- weight pre-rounding to tf32 ----------------
__global__ void round_weights(const float* __restrict__ Win, const float* __restrict__ Wx,
                              const float* __restrict__ Wdt, const float* __restrict__ Wout,
                              float* __restrict__ rWin, float* __restrict__ rWx,
                              float* __restrict__ rWdt, float* __restrict__ rWout)
{
    int i = blockIdx.x * 256 + threadIdx.x;
    if (i < N_WIN) { rWin[i] = to_tf32(Win[i]); return; }
    i -= N_WIN;
    if (i < N_WX)  { rWx[i]  = to_tf32(Wx[i]);  return; }
    i -= N_WX;
    if (i < N_WDT) { rWdt[i] = to_tf32(Wdt[i]); return; }
    i -= N_WDT;
    if (i < N_WOUT) rWout[i] = to_tf32(Wout[i]);
}

// ---------------- LayerNorm (tf32-rounded output) ----------------
__global__ void ln_kernel(const float* __restrict__ x, const float* __restrict__ g,
                          const float* __restrict__ b, float* __restrict__ xn)
{
    int t = blockIdx.x;
    const float* xr = x + t * D_MODEL;
    float s = 0.f, s2 = 0.f;
    for (int i = threadIdx.x; i < D_MODEL; i += 256) {
        float v = xr[i];
        s += v; s2 += v * v;
    }
    #pragma unroll
    for (int o = 16; o; o >>= 1) {
        s  += __shfl_xor_sync(0xffffffffu, s,  o);
        s2 += __shfl_xor_sync(0xffffffffu, s2, o);
    }
    __shared__ float ss[8], ss2[8];
    __shared__ float mu_s, rstd_s;
    if ((threadIdx.x & 31) == 0) { ss[threadIdx.x >> 5] = s; ss2[threadIdx.x >> 5] = s2; }
    __syncthreads();
    if (threadIdx.x == 0) {
        float a = 0.f, a2 = 0.f;
        #pragma unroll
        for (int i = 0; i < 8; i++) { a += ss[i]; a2 += ss2[i]; }
        float mu = a / (float)D_MODEL;
        float var = a2 / (float)D_MODEL - mu * mu;
        mu_s = mu;
        rstd_s = rsqrtf(var + LN_EPS);
    }
    __syncthreads();
    float mu = mu_s, rstd = rstd_s;
    for (int i = threadIdx.x; i < D_MODEL; i += 256)
        xn[t * D_MODEL + i] = to_tf32((xr[i] - mu) * rstd * g[i] + b[i]);
}

// ---------------- tf32 WMMA GEMM: 3-stage cp.async pipeline, fused split-K reduce ----------------
// epilogue: 0 = plain; 1 = softplus(v + bias[col]) + TRANSPOSED store (ldc = transposed ld)
// dtr: if non-null (split-K path), rounded copy of columns < DT_RANK is also written.
template<int BM, int BN, int BK>
__global__ void __launch_bounds__(GEMM_THREADS)
gemm_tf32(const float* __restrict__ A, int lda,
          const float* __restrict__ B, int ldb,
          float* __restrict__ part, float* __restrict__ Cfinal, int ldc,
          int M, int N, int K, int Kslice,
          const float* __restrict__ bias, int epilogue,
          float* __restrict__ dtr)
{
    constexpr int ALD = BK + 4;
    constexpr int BLD = BN + 4;
    constexpr int CLD = BN + 4;
    constexpr int FM = BM / 4 / 16;
    constexpr int FN = BN / 2 / 16;
    constexpr int STAGE_F = BM*ALD + BK*BLD;

    extern __shared__ float smem[];

    const int tid  = threadIdx.x;
    const int warp = tid >> 5;
    const int wr   = warp >> 1;
    const int wc   = warp & 1;
    const int row_base = blockIdx.y * BM;
    const int col_base = blockIdx.x * BN;

    const int k_begin = blockIdx.z * Kslice;
    const int k_end   = min(K, k_begin + Kslice);

    const float4 zero4 = make_float4(0.f, 0.f, 0.f, 0.f);

    auto load_stage = [&](int s, int k0) {
        float* As = smem + s * STAGE_F;
        float* Bs = As + BM*ALD;
        #pragma unroll
        for (int i = 0; i < BM*BK/4/GEMM_THREADS; i++) {
            int idx = tid + i * GEMM_THREADS;
            int r = idx / (BK/4), ch = idx % (BK/4);
            int gc = k0 + ch * 4;
            float* dst = &As[r * ALD + ch * 4];
            if (gc + 4 <= k_end) cp_async16(dst, &A[(row_base + r) * (size_t)lda + gc]);
            else                 *(float4*)dst = zero4;
        }
        #pragma unroll
        for (int i = 0; i < BK*BN/4/GEMM_THREADS; i++) {
            int idx = tid + i * GEMM_THREADS;
            int r = idx / (BN/4), ch = idx % (BN/4);
            int gr = k0 + r, gc = col_base + ch * 4;
            float* dst = &Bs[r * BLD + ch * 4];
            if (gr < k_end && gc + 4 <= N) cp_async16(dst, &B[gr * (size_t)ldb + gc]);
            else                           *(float4*)dst = zero4;
        }
        cp_async_commit();
    };

    wmma::fragment<wmma::accumulator, 16, 16, 8, float> acc[FM][FN];
    #pragma unroll
    for (int i = 0; i < FM; i++)
        #pragma unroll
        for (int j = 0; j < FN; j++)
            wmma::fill_fragment(acc[i][j], 0.f);

    const int ntiles = (k_end - k_begin + BK - 1) / BK;
    load_stage(0, k_begin);
    if (ntiles > 1) load_stage(1, k_begin + BK);

    for (int kt = 0; kt < ntiles; kt++) {
        int s = kt % STAGES;
        if (kt + 2 < ntiles) {
            load_stage((kt + 2) % STAGES, k_begin + (kt + 2) * BK);
            cp_async_wait<STAGES - 1>();
        } else {
            cp_async_wait<0>();
        }
        __syncthreads();

        const float* Ac = smem + s * STAGE_F;
        const float* Bc = Ac + BM*ALD;
        #pragma unroll
        for (int kk = 0; kk < BK; kk += 8) {
            wmma::fragment<wmma::matrix_a, 16, 16, 8, wmma::precision::tf32, wmma::row_major> af[FM];
            wmma::fragment<wmma::matrix_b, 16, 16, 8, wmma::precision::tf32, wmma::row_major> bf[FN];
            #pragma unroll
            for (int i = 0; i < FM; i++)
                wmma::load_matrix_sync(af[i], &Ac[(wr * (BM/4) + i * 16) * ALD + kk], ALD);
            #pragma unroll
            for (int j = 0; j < FN; j++)
                wmma::load_matrix_sync(bf[j], &Bc[kk * BLD + wc * (BN/2) + j * 16], BLD);
            #pragma unroll
            for (int i = 0; i < FM; i++)
                #pragma unroll
                for (int j = 0; j < FN; j++)
                    wmma::mma_sync(acc[i][j], af[i], bf[j], acc[i][j]);
        }
        __syncthreads();
    }

    float* Cs = smem;
    #pragma unroll
    for (int i = 0; i < FM; i++)
        #pragma unroll
        for (int j = 0; j < FN; j++)
            wmma::store_matrix_sync(&Cs[(wr * (BM/4) + i * 16) * CLD + wc * (BN/2) + j * 16],
                                    acc[i][j], CLD, wmma::mem_row_major);
    __syncthreads();

    if (gridDim.z == 1) {
        if (epilogue == 1) {
            #pragma unroll
            for (int e = tid; e < BM * BN; e += GEMM_THREADS) {
                int tl = e % BM, dl = e / BM;
                int gr = row_base + tl, gc = col_base + dl;
                if (gr < M && gc < N) {
                    float v = Cs[tl * CLD + dl] + bias[gc];
                    v = fmaxf(v, 0.f) + log1pf(__expf(-fabsf(v)));
                    Cfinal[gc * (size_t)ldc + gr] = v;
                }
            }
        } else {
            #pragma unroll
            for (int e = tid; e < BM * BN; e += GEMM_THREADS) {
                int r = e / BN, c = e % BN;
                int gr = row_base + r, gc = col_base + c;
                if (gr < M && gc < N)
                    Cfinal[gr * (size_t)ldc + gc] = Cs[r * CLD + c];
            }
        }
        return;
    }

    // ---- fused split-K: write partial, last CTA reduces deterministically ----
    float* myp = part + (size_t)blockIdx.z * M * ldc;
    #pragma unroll
    for (int e = tid; e < BM * BN; e += GEMM_THREADS) {
        int r = e / BN, c = e % BN;
        int gr = row_base + r, gc = col_base + c;
        if (gr < M && gc < N)
            myp[gr * (size_t)ldc + gc] = Cs[r * CLD + c];
    }
    __threadfence();
    __syncthreads();

    __shared__ int is_last;
    const int tile = blockIdx.y * gridDim.x + blockIdx.x;
    if (tid == 0)
        is_last = (atomicAdd(&g_cnt[tile], 1) == (int)gridDim.z - 1);
    __syncthreads();
    if (!is_last) return;
    __threadfence();

    const int nz = gridDim.z;
    for (int e = tid; e < BM * BN; e += GEMM_THREADS) {
        int r = e / BN, c = e % BN;
        int gr = row_base + r, gc = col_base + c;
        if (gr < M && gc < N) {
            size_t off = gr * (size_t)ldc + gc;
            float v = 0.f;
            for (int z = 0; z < nz; z++)
                v += part[(size_t)z * M * ldc + off];
            Cfinal[off] = v;
            if (dtr && gc < DT_RANK)
                dtr[gr * DT_RANK + gc] = to_tf32(v);
        }
    }
    if (tid == 0) g_cnt[tile] = 0;
}

// ---------------- conv(d_conv=4)+SiLU -> xc (rounded), xcT  and  silu(z) -> zsT ----------------
// tile: 32 channels x 128 timesteps (R10 form)
__global__ void conv_fused_kernel(const float* __restrict__ xz,
                                  const float* __restrict__ conv_w,
                                  const float* __restrict__ conv_b,
                                  float* __restrict__ xc,
                                  float* __restrict__ xcT,
                                  float* __restrict__ zsT)
{
    __shared__ float xs[131][33];
    __shared__ float buf[128][33];
    const int tx = threadIdx.x, ty = threadIdx.y;
    const int d0 = blockIdx.x * 32;
    const int t0 = blockIdx.y * 128;
    const int d  = d0 + tx;

    for (int i = ty; i < 131; i += 8) {
        int t = t0 - 3 + i;
        xs[i][tx] = (t >= 0) ? xz[t * (2 * D_INNER) + d] : 0.f;
    }
    const float w0 = conv_w[d * D_CONV + 0];
    const float w1 = conv_w[d * D_CONV + 1];
    const float w2 = conv_w[d * D_CONV + 2];
    const float w3 = conv_w[d * D_CONV + 3];
    const float cb = conv_b[d];
    __syncthreads();

    for (int i = ty; i < 128; i += 8) {
        float acc = cb + xs[i][tx] * w0 + xs[i+1][tx] * w1 + xs[i+2][tx] * w2 + xs[i+3][tx] * w3;
        acc = acc * __frcp_rn(1.f + __expf(-acc));   // silu
        xc[(t0 + i) * D_INNER + d] = to_tf32(acc);
        buf[i][tx] = acc;
    }
    __syncthreads();
    #pragma unroll
    for (int jj = 0; jj < 4; jj++) {
        int t = tx + jj * 32;
        for (int i = ty; i < 32; i += 8)
            xcT[(d0 + i) * (size_t)L_SEQ + t0 + t] = buf[t][i];
    }
    __syncthreads();
    for (int i = ty; i < 128; i += 8) {
        float v = xz[(t0 + i) * (2 * D_INNER) + D_INNER + d];
        buf[i][tx] = v * __frcp_rn(1.f + __expf(-v));
    }
    __syncthreads();
    #pragma unroll
    for (int jj = 0; jj < 4; jj++) {
        int t = tx + jj * 32;
        for (int i = ty; i < 32; i += 8)
            zsT[(d0 + i) * (size_t)L_SEQ + t0 + t] = buf[t][i];
    }
}

// ---------------- chunked scan, pass 1 + fused combine (last CTA per dblock) ----------------
__global__ void scan_pass1(const float* __restrict__ dbl,
                           const float* __restrict__ dtT,
                           const float* __restrict__ xcT,
                           const float* __restrict__ A_log,
                           float* __restrict__ cumA,
                           float* __restrict__ hp,
                           float* __restrict__ hinit)
{
    __shared__ float bc[32][65];
    const int warp = threadIdx.x >> 5, lane = threadIdx.x & 31;
    const int d   = blockIdx.x * 8 + warp;
    const int seg = blockIdx.y;
    const int t0  = seg * SEG;

    const float A0 = -__expf(A_log[d * D_STATE + lane]);
    const float A1 = -__expf(A_log[d * D_STATE + lane + 32]);
    float h0 = 0.f, h1 = 0.f, p0 = 1.f, p1 = 1.f;

    for (int tc = t0; tc < t0 + SEG; tc += 32) {
        float dt_r = dtT[d * L_SEQ + tc + lane];
        float xc_r = xcT[d * L_SEQ + tc + lane];
        __syncthreads();
        for (int e = threadIdx.x; e < 32 * 64; e += 256) {
            int r = e >> 6, c = e & 63;
            bc[r][c] = dbl[(tc + r) * DBL_N + DT_RANK + c];
        }
        __syncthreads();

        #pragma unroll
        for (int js = 0; js < 32; js += 8) {
            float dA0[8], dA1[8], dxb0[8], dxb1[8];
            #pragma unroll
            for (int j = 0; j < 8; j++) {
                float dt_t = __shfl_sync(0xffffffffu, dt_r, js + j);
                float x_t  = __shfl_sync(0xffffffffu, xc_r, js + j);
                dA0[j] = __expf(dt_t * A0);
                dA1[j] = __expf(dt_t * A1);
                float dx = dt_t * x_t;
                dxb0[j] = dx * bc[js + j][lane];
                dxb1[j] = dx * bc[js + j][lane + 32];
            }
            #pragma unroll
            for (int j = 0; j < 8; j++) {
                h0 = fmaf(dA0[j], h0, dxb0[j]);
                h1 = fmaf(dA1[j], h1, dxb1[j]);
                p0 *= dA0[j];
                p1 *= dA1[j];
            }
        }
    }
    const int base = (seg * D_INNER + d) * D_STATE;
    cumA[base + lane]      = p0;
    cumA[base + lane + 32] = p1;
    hp  [base + lane]      = h0;
    hp  [base + lane + 32] = h1;

    // ---- fused combine: last seg-CTA of this dblock builds hinit chains ----
    __threadfence();
    __syncthreads();
    __shared__ int is_last;
    if (threadIdx.x == 0)
        is_last = (atomicAdd(&g_cnt[256 + blockIdx.x], 1) == NSEG - 1);
    __syncthreads();
    if (!is_last) return;
    __threadfence();

    for (int e = threadIdx.x; e < 8 * D_STATE; e += 256) {
        int dl = e >> 6, n = e & 63;
        int off = (blockIdx.x * 8 + dl) * D_STATE + n;
        float h = 0.f;
        #pragma unroll
        for (int s = 0; s < NSEG; s++) {
            hinit[s * DN + off] = h;
            h = fmaf(cumA[s * DN + off], h, hp[s * DN + off]);
        }
    }
    if (threadIdx.x == 0) g_cnt[256 + blockIdx.x] = 0;
}

// ---------------- chunked scan, pass 2 ----------------
__global__ void scan_pass2(const float* __restrict__ dbl,
                           const float* __restrict__ dtT,
                           const float* __restrict__ xcT,
                           const float* __restrict__ zsT,
                           const float* __restrict__ A_log,
                           const float* __restrict__ D_skip,
                           const float* __restrict__ hinit,
                           float* __restrict__ y)
{
    __shared__ float bc[32][129];
    const int warp = threadIdx.x >> 5, lane = threadIdx.x & 31;
    const int d   = blockIdx.x * 8 + warp;
    const int seg = blockIdx.y;
    const int t0  = seg * SEG;

    const float A0 = -__expf(A_log[d * D_STATE + lane]);
    const float A1 = -__expf(A_log[d * D_STATE + lane + 32]);
    const float Dd = D_skip[d];
    float h0 = hinit[seg * DN + d * D_STATE + lane];
    float h1 = hinit[seg * DN + d * D_STATE + lane + 32];

    for (int tc = t0; tc < t0 + SEG; tc += 32) {
        float dt_r = dtT[d * L_SEQ + tc + lane];
        float xc_r = xcT[d * L_SEQ + tc + lane];
        float zs_r = zsT[d * L_SEQ + tc + lane];
        __syncthreads();
        for (int e = threadIdx.x; e < 32 * 128; e += 256) {
            int r = e >> 7, c = e & 127;
            bc[r][c] = dbl[(tc + r) * DBL_N + DT_RANK + c];
        }
        __syncthreads();

        #pragma unroll
        for (int js = 0; js < 32; js += 8) {
            float dA0[8], dA1[8], dxb0[8], dxb1[8], cc0[8], cc1[8];
            #pragma unroll
            for (int j = 0; j < 8; j++) {
                float dt_t = __shfl_sync(0xffffffffu, dt_r, js + j);
                float x_t  = __shfl_sync(0xffffffffu, xc_r, js + j);
                dA0[j] = __expf(dt_t * A0);
                dA1[j] = __expf(dt_t * A1);
                float dx = dt_t * x_t;
                dxb0[j] = dx * bc[js + j][lane];
                dxb1[j] = dx * bc[js + j][lane + 32];
                cc0[j]  = bc[js + j][64 + lane];
                cc1[j]  = bc[js + j][96 + lane];
            }
            float ys[8];
            #pragma unroll
            for (int j = 0; j < 8; j++) {
                h0 = fmaf(dA0[j], h0, dxb0[j]);
                h1 = fmaf(dA1[j], h1, dxb1[j]);
                ys[j] = h0 * cc0[j] + h1 * cc1[j];
            }
            #pragma unroll
            for (int o = 16; o; o >>= 1) {
                #pragma unroll
                for (int j = 0; j < 8; j++)
                    ys[j] += __shfl_xor_sync(0xffffffffu, ys[j], o);
            }
            float x_l  = __shfl_sync(0xffffffffu, xc_r, js + (lane & 7));
            float zs_l = __shfl_sync(0xffffffffu, zs_r, js + (lane & 7));
            float yv = ys[0];
            #pragma unroll
            for (int j = 1; j < 8; j++)
                yv = (lane == j) ? ys[j] : yv;
            if (lane < 8) {
                int t = tc + js + lane;
                y[t * D_INNER + d] = to_tf32((yv + x_l * Dd) * zs_l);
            }
        }
    }
}

// ---------------- host launcher ----------------
static constexpr int smem_bytes(int BM, int BN, int BK) {
    return (BM * (BK + 4) + BK * (BN + 4)) * STAGES * 4;
}

extern "C" void kernel_launch(void* const* d_in, const int* in_sizes, int n_in,
                              void* d_out, int out_size)
{
    const float* x      = (const float*)d_in[0];
    const float* ln_g   = (const float*)d_in[1];
    const float* ln_b   = (const float*)d_in[2];
    const float* W_in   = (const float*)d_in[3];
    const float* conv_w = (const float*)d_in[4];
    const float* conv_b = (const float*)d_in[5];
    const float* W_x    = (const float*)d_in[6];
    const float* W_dt   = (const float*)d_in[7];
    const float* b_dt   = (const float*)d_in[8];
    const float* A_log  = (const float*)d_in[9];
    const float* D_skip = (const float*)d_in[10];
    const float* W_out  = (const float*)d_in[11];
    float* out = (float*)d_out;

    float *xn, *xz, *xc, *dbl, *dblr, *xcT, *dtT, *zsT, *y, *part;
    float *cumA, *hp, *hinit, *rWin, *rWx, *rWdt, *rWout;
    cudaGetSymbolAddress((void**)&xn,    g_xn);
    cudaGetSymbolAddress((void**)&xz,    g_xz);
    cudaGetSymbolAddress((void**)&xc,    g_xc);
    cudaGetSymbolAddress((void**)&dbl,   g_dbl);
    cudaGetSymbolAddress((void**)&dblr,  g_dblr);
    cudaGetSymbolAddress((void**)&xcT,   g_xcT);
    cudaGetSymbolAddress((void**)&dtT,   g_dtT);
    cudaGetSymbolAddress((void**)&zsT,   g_zsT);
    cudaGetSymbolAddress((void**)&y,     g_y);
    cudaGetSymbolAddress((void**)&part,  g_part);
    cudaGetSymbolAddress((void**)&cumA,  g_cumA);
    cudaGetSymbolAddress((void**)&hp,    g_hp);
    cudaGetSymbolAddress((void**)&hinit, g_hinit);
    cudaGetSymbolAddress((void**)&rWin,  g_rWin);
    cudaGetSymbolAddress((void**)&rWx,   g_rWx);
    cudaGetSymbolAddress((void**)&rWdt,  g_rWdt);
    cudaGetSymbolAddress((void**)&rWout, g_rWout);

    constexpr int SM_BIGN = smem_bytes(64, 128, 32);  // 78336
    constexpr int SM_SM   = smem_bytes(64, 64, 32);   // 53760

    static bool attr_done = false;
    if (!attr_done) {
        cudaFuncSetAttribute(gemm_tf32<64,128,32>, cudaFuncAttributeMaxDynamicSharedMemorySize, SM_BIGN);
        cudaFuncSetAttribute(gemm_tf32<64,64,32>,  cudaFuncAttributeMaxDynamicSharedMemorySize, SM_SM);
        attr_done = true;
    }

    // 0. pre-round weights to tf32
    round_weights<<<(N_WIN + N_WX + N_WDT + N_WOUT + 255) / 256, 256>>>(
        W_in, W_x, W_dt, W_out, rWin, rWx, rWdt, rWout);

    // 1. LayerNorm (rounded output)
    ln_kernel<<<L_SEQ, 256>>>(x, ln_g, ln_b, xn);

    // 2. in-projection: xz = xn @ W_in  (M=1024, N=3072, K=768) -> 768 CTAs (BN=64)
    gemm_tf32<64,64,32><<<dim3(2 * D_INNER / 64, L_SEQ / 64, 1), GEMM_THREADS, SM_SM>>>(
        xn, D_MODEL, rWin, 2 * D_INNER, nullptr, xz, 2 * D_INNER,
        L_SEQ, 2 * D_INNER, D_MODEL, D_MODEL, nullptr, 0, nullptr);

    // 3. conv+SiLU -> xc (rounded), xcT;  silu(z) -> zsT  (384 CTAs, 128-step tile)
    conv_fused_kernel<<<dim3(D_INNER / 32, L_SEQ / 128), dim3(32, 8)>>>(
        xz, conv_w, conv_b, xc, xcT, zsT);

    // 4. x-projection: dbl = xc @ W_x  (split-K=8) -> 384 CTAs; emits rounded dt_raw
    gemm_tf32<64,64,32><<<dim3(3, L_SEQ / 64, 8), GEMM_THREADS, SM_SM>>>(
        xc, D_INNER, rWx, DBL_N, part, dbl, DBL_N,
        L_SEQ, DBL_N, D_INNER, D_INNER / 8, nullptr, 0, dblr);

    // 5. dtT = softplus(dt_raw @ W_dt + b_dt)^T -> 384 CTAs
    gemm_tf32<64,64,32><<<dim3(D_INNER / 64, L_SEQ / 64, 1), GEMM_THREADS, SM_SM>>>(
        dblr, DT_RANK, rWdt, D_INNER, nullptr, dtT, L_SEQ,
        L_SEQ, D_INNER, DT_RANK, DT_RANK, b_dt, 1, nullptr);

    // 6-7. chunked selective scan (combine fused into pass1)
    scan_pass1<<<dim3(D_INNER / 8, NSEG), 256>>>(dbl, dtT, xcT, A_log, cumA, hp, hinit);
    scan_pass2<<<dim3(D_INNER / 8, NSEG), 256>>>(dbl, dtT, xcT, zsT, A_log, D_skip, hinit, y);

    // 8. out-projection: out = y @ W_out  (split-K=4) -> 384 CTAs
    gemm_tf32<64,128,32><<<dim3(D_MODEL / 128, L_SEQ / 64, 4), GEMM_THREADS, SM_BIGN>>>(
        y, D_INNER, rWout, D_MODEL, part, out, D_MODEL,
        L_SEQ, D_MODEL, D_INNER, D_INNER / 4, nullptr, 0, nullptr);
}

// round 13
// speedup vs baseline: 1.0584x; 1.0584x over previous
#include <cstdint>
#include <cuda_runtime.h>
#include <cuda_bf16.h>
#include <mma.h>

using namespace nvcuda;

// ---------------- problem constants ----------------
#define L_SEQ   1024
#define D_MODEL 768
#define D_INNER 1536
#define D_STATE 64
#define D_CONV  4
#define DT_RANK 48
#define DBL_N   (DT_RANK + 2*D_STATE)   // 176
#define LN_EPS  1e-5f

#define GEMM_THREADS 256

// chunked scan
#define NSEG 8
#define SEG  (L_SEQ / NSEG)             // 128
#define DN   (D_INNER * D_STATE)        // 98304

// weight sizes
#define N_WIN  (D_MODEL * 2 * D_INNER)
#define N_WX   (D_INNER * DBL_N)
#define N_WDT  (DT_RANK * D_INNER)
#define N_WOUT (D_INNER * D_MODEL)

// ---------------- scratch (no allocations allowed) ----------------
__device__ float g_xn [L_SEQ * D_MODEL];
__device__ float g_xz [L_SEQ * 2 * D_INNER];
__device__ float g_xc [L_SEQ * D_INNER];
__device__ float g_dbl[L_SEQ * DBL_N];
__device__ float g_dblr[L_SEQ * DT_RANK];
__device__ float g_xcT[D_INNER * L_SEQ];
__device__ float g_dtT[D_INNER * L_SEQ];
__device__ float g_zsT[D_INNER * L_SEQ];
__device__ float g_y  [L_SEQ * D_INNER];
__device__ float g_part[8 * L_SEQ * DBL_N > 4 * L_SEQ * D_MODEL ?
                        8 * L_SEQ * DBL_N : 4 * L_SEQ * D_MODEL];
__device__ float g_cumA [NSEG * DN];
__device__ float g_hp   [NSEG * DN];
__device__ float g_hinit[NSEG * DN];
__device__ float g_rWin [N_WIN];
__device__ float g_rWx  [N_WX];
__device__ float g_rWdt [N_WDT];
__device__ float g_rWout[N_WOUT];
__device__ int   g_cnt[512];

// ---------------- helpers ----------------
__device__ __forceinline__ float to_tf32(float x) {
    float r;
    asm("cvt.rna.tf32.f32 %0, %1;" : "=f"(r) : "f"(x));
    return r;
}
__device__ __forceinline__ void cp_async16(void* smem_dst, const void* gmem_src) {
    unsigned int dst = (unsigned int)__cvta_generic_to_shared(smem_dst);
    asm volatile("cp.async.cg.shared.global [%0], [%1], 16;\n" :: "r"(dst), "l"(gmem_src));
}
__device__ __forceinline__ void cp_async_commit() {
    asm volatile("cp.async.commit_group;\n");
}
template<int N>
__device__ __forceinline__ void cp_async_wait() {
    asm volatile("cp.async.wait_group %0;\n" :: "n"(N));
}

// ---------------- weight pre-rounding to tf32 ----------------
__global__ void round_weights(const float* __restrict__ Win, const float* __restrict__ Wx,
                              const float* __restrict__ Wdt, const float* __restrict__ Wout,
                              float* __restrict__ rWin, float* __restrict__ rWx,
                              float* __restrict__ rWdt, float* __restrict__ rWout)
{
    int i = blockIdx.x * 256 + threadIdx.x;
    if (i < N_WIN) { rWin[i] = to_tf32(Win[i]); return; }
    i -= N_WIN;
    if (i < N_WX)  { rWx[i]  = to_tf32(Wx[i]);  return; }
    i -= N_WX;
    if (i < N_WDT) { rWdt[i] = to_tf32(Wdt[i]); return; }
    i -= N_WDT;
    if (i < N_WOUT) rWout[i] = to_tf32(Wout[i]);
}

// ---------------- LayerNorm (tf32-rounded output) ----------------
__global__ void ln_kernel(const float* __restrict__ x, const float* __restrict__ g,
                          const float* __restrict__ b, float* __restrict__ xn)
{
    int t = blockIdx.x;
    const float* xr = x + t * D_MODEL;
    float s = 0.f, s2 = 0.f;
    for (int i = threadIdx.x; i < D_MODEL; i += 256) {
        float v = xr[i];
        s += v; s2 += v * v;
    }
    #pragma unroll
    for (int o = 16; o; o >>= 1) {
        s  += __shfl_xor_sync(0xffffffffu, s,  o);
        s2 += __shfl_xor_sync(0xffffffffu, s2, o);
    }
    __shared__ float ss[8], ss2[8];
    __shared__ float mu_s, rstd_s;
    if ((threadIdx.x & 31) == 0) { ss[threadIdx.x >> 5] = s; ss2[threadIdx.x >> 5] = s2; }
    __syncthreads();
    if (threadIdx.x == 0) {
        float a = 0.f, a2 = 0.f;
        #pragma unroll
        for (int i = 0; i < 8; i++) { a += ss[i]; a2 += ss2[i]; }
        float mu = a / (float)D_MODEL;
        float var = a2 / (float)D_MODEL - mu * mu;
        mu_s = mu;
        rstd_s = rsqrtf(var + LN_EPS);
    }
    __syncthreads();
    float mu = mu_s, rstd = rstd_s;
    for (int i = threadIdx.x; i < D_MODEL; i += 256)
        xn[t * D_MODEL + i] = to_tf32((xr[i] - mu) * rstd * g[i] + b[i]);
}

// ---------------- tf32 WMMA GEMM: NST-stage cp.async pipeline, fused split-K reduce ----------------
// epilogue: 0 = plain; 1 = softplus(v + bias[col]) + TRANSPOSED store (ldc = transposed ld)
// dtr: if non-null (split-K path), rounded copy of columns < DT_RANK is also written.
template<int BM, int BN, int BK, int NST>
__global__ void __launch_bounds__(GEMM_THREADS)
gemm_tf32(const float* __restrict__ A, int lda,
          const float* __restrict__ B, int ldb,
          float* __restrict__ part, float* __restrict__ Cfinal, int ldc,
          int M, int N, int K, int Kslice,
          const float* __restrict__ bias, int epilogue,
          float* __restrict__ dtr)
{
    constexpr int ALD = BK + 4;
    constexpr int BLD = BN + 4;
    constexpr int CLD = BN + 4;
    constexpr int FM = BM / 4 / 16;
    constexpr int FN = BN / 2 / 16;
    constexpr int STAGE_F = BM*ALD + BK*BLD;

    extern __shared__ float smem[];

    const int tid  = threadIdx.x;
    const int warp = tid >> 5;
    const int wr   = warp >> 1;
    const int wc   = warp & 1;
    const int row_base = blockIdx.y * BM;
    const int col_base = blockIdx.x * BN;

    const int k_begin = blockIdx.z * Kslice;
    const int k_end   = min(K, k_begin + Kslice);

    const float4 zero4 = make_float4(0.f, 0.f, 0.f, 0.f);

    auto load_stage = [&](int s, int k0) {
        float* As = smem + s * STAGE_F;
        float* Bs = As + BM*ALD;
        #pragma unroll
        for (int i = 0; i < BM*BK/4/GEMM_THREADS; i++) {
            int idx = tid + i * GEMM_THREADS;
            int r = idx / (BK/4), ch = idx % (BK/4);
            int gc = k0 + ch * 4;
            float* dst = &As[r * ALD + ch * 4];
            if (gc + 4 <= k_end) cp_async16(dst, &A[(row_base + r) * (size_t)lda + gc]);
            else                 *(float4*)dst = zero4;
        }
        #pragma unroll
        for (int i = 0; i < BK*BN/4/GEMM_THREADS; i++) {
            int idx = tid + i * GEMM_THREADS;
            int r = idx / (BN/4), ch = idx % (BN/4);
            int gr = k0 + r, gc = col_base + ch * 4;
            float* dst = &Bs[r * BLD + ch * 4];
            if (gr < k_end && gc + 4 <= N) cp_async16(dst, &B[gr * (size_t)ldb + gc]);
            else                           *(float4*)dst = zero4;
        }
        cp_async_commit();
    };

    wmma::fragment<wmma::accumulator, 16, 16, 8, float> acc[FM][FN];
    #pragma unroll
    for (int i = 0; i < FM; i++)
        #pragma unroll
        for (int j = 0; j < FN; j++)
            wmma::fill_fragment(acc[i][j], 0.f);

    const int ntiles = (k_end - k_begin + BK - 1) / BK;
    #pragma unroll
    for (int p = 0; p < NST - 1; p++)
        if (p < ntiles) load_stage(p, k_begin + p * BK);

    for (int kt = 0; kt < ntiles; kt++) {
        int s = kt % NST;
        if (kt + NST - 1 < ntiles) {
            load_stage((kt + NST - 1) % NST, k_begin + (kt + NST - 1) * BK);
            cp_async_wait<NST - 1>();
        } else {
            cp_async_wait<0>();
        }
        __syncthreads();

        const float* Ac = smem + s * STAGE_F;
        const float* Bc = Ac + BM*ALD;
        #pragma unroll
        for (int kk = 0; kk < BK; kk += 8) {
            wmma::fragment<wmma::matrix_a, 16, 16, 8, wmma::precision::tf32, wmma::row_major> af[FM];
            wmma::fragment<wmma::matrix_b, 16, 16, 8, wmma::precision::tf32, wmma::row_major> bf[FN];
            #pragma unroll
            for (int i = 0; i < FM; i++)
                wmma::load_matrix_sync(af[i], &Ac[(wr * (BM/4) + i * 16) * ALD + kk], ALD);
            #pragma unroll
            for (int j = 0; j < FN; j++)
                wmma::load_matrix_sync(bf[j], &Bc[kk * BLD + wc * (BN/2) + j * 16], BLD);
            #pragma unroll
            for (int i = 0; i < FM; i++)
                #pragma unroll
                for (int j = 0; j < FN; j++)
                    wmma::mma_sync(acc[i][j], af[i], bf[j], acc[i][j]);
        }
        __syncthreads();
    }

    float* Cs = smem;
    #pragma unroll
    for (int i = 0; i < FM; i++)
        #pragma unroll
        for (int j = 0; j < FN; j++)
            wmma::store_matrix_sync(&Cs[(wr * (BM/4) + i * 16) * CLD + wc * (BN/2) + j * 16],
                                    acc[i][j], CLD, wmma::mem_row_major);
    __syncthreads();

    if (gridDim.z == 1) {
        if (epilogue == 1) {
            #pragma unroll
            for (int e = tid; e < BM * BN; e += GEMM_THREADS) {
                int tl = e % BM, dl = e / BM;
                int gr = row_base + tl, gc = col_base + dl;
                if (gr < M && gc < N) {
                    float v = Cs[tl * CLD + dl] + bias[gc];
                    v = fmaxf(v, 0.f) + log1pf(__expf(-fabsf(v)));
                    Cfinal[gc * (size_t)ldc + gr] = v;
                }
            }
        } else {
            #pragma unroll
            for (int e = tid; e < BM * BN; e += GEMM_THREADS) {
                int r = e / BN, c = e % BN;
                int gr = row_base + r, gc = col_base + c;
                if (gr < M && gc < N)
                    Cfinal[gr * (size_t)ldc + gc] = Cs[r * CLD + c];
            }
        }
        return;
    }

    // ---- fused split-K: write partial, last CTA reduces deterministically ----
    float* myp = part + (size_t)blockIdx.z * M * ldc;
    #pragma unroll
    for (int e = tid; e < BM * BN; e += GEMM_THREADS) {
        int r = e / BN, c = e % BN;
        int gr = row_base + r, gc = col_base + c;
        if (gr < M && gc < N)
            myp[gr * (size_t)ldc + gc] = Cs[r * CLD + c];
    }
    __threadfence();
    __syncthreads();

    __shared__ int is_last;
    const int tile = blockIdx.y * gridDim.x + blockIdx.x;
    if (tid == 0)
        is_last = (atomicAdd(&g_cnt[tile], 1) == (int)gridDim.z - 1);
    __syncthreads();
    if (!is_last) return;
    __threadfence();

    const int nz = gridDim.z;
    for (int e = tid; e < BM * BN; e += GEMM_THREADS) {
        int r = e / BN, c = e % BN;
        int gr = row_base + r, gc = col_base + c;
        if (gr < M && gc < N) {
            size_t off = gr * (size_t)ldc + gc;
            float v = 0.f;
            for (int z = 0; z < nz; z++)
                v += part[(size_t)z * M * ldc + off];
            Cfinal[off] = v;
            if (dtr && gc < DT_RANK)
                dtr[gr * DT_RANK + gc] = to_tf32(v);
        }
    }
    if (tid == 0) g_cnt[tile] = 0;
}

// ---------------- conv(d_conv=4)+SiLU -> xc (rounded), xcT  and  silu(z) -> zsT ----------------
__global__ void conv_fused_kernel(const float* __restrict__ xz,
                                  const float* __restrict__ conv_w,
                                  const float* __restrict__ conv_b,
                                  float* __restrict__ xc,
                                  float* __restrict__ xcT,
                                  float* __restrict__ zsT)
{
    __shared__ float xs[131][33];
    __shared__ float buf[128][33];
    const int tx = threadIdx.x, ty = threadIdx.y;
    const int d0 = blockIdx.x * 32;
    const int t0 = blockIdx.y * 128;
    const int d  = d0 + tx;

    for (int i = ty; i < 131; i += 8) {
        int t = t0 - 3 + i;
        xs[i][tx] = (t >= 0) ? xz[t * (2 * D_INNER) + d] : 0.f;
    }
    const float w0 = conv_w[d * D_CONV + 0];
    const float w1 = conv_w[d * D_CONV + 1];
    const float w2 = conv_w[d * D_CONV + 2];
    const float w3 = conv_w[d * D_CONV + 3];
    const float cb = conv_b[d];
    __syncthreads();

    for (int i = ty; i < 128; i += 8) {
        float acc = cb + xs[i][tx] * w0 + xs[i+1][tx] * w1 + xs[i+2][tx] * w2 + xs[i+3][tx] * w3;
        acc = acc * __frcp_rn(1.f + __expf(-acc));   // silu
        xc[(t0 + i) * D_INNER + d] = to_tf32(acc);
        buf[i][tx] = acc;
    }
    __syncthreads();
    #pragma unroll
    for (int jj = 0; jj < 4; jj++) {
        int t = tx + jj * 32;
        for (int i = ty; i < 32; i += 8)
            xcT[(d0 + i) * (size_t)L_SEQ + t0 + t] = buf[t][i];
    }
    __syncthreads();
    for (int i = ty; i < 128; i += 8) {
        float v = xz[(t0 + i) * (2 * D_INNER) + D_INNER + d];
        buf[i][tx] = v * __frcp_rn(1.f + __expf(-v));
    }
    __syncthreads();
    #pragma unroll
    for (int jj = 0; jj < 4; jj++) {
        int t = tx + jj * 32;
        for (int i = ty; i < 32; i += 8)
            zsT[(d0 + i) * (size_t)L_SEQ + t0 + t] = buf[t][i];
    }
}

// ---------------- chunked scan, pass 1 (float4 staging) ----------------
__global__ void scan_pass1(const float* __restrict__ dbl,
                           const float* __restrict__ dtT,
                           const float* __restrict__ xcT,
                           const float* __restrict__ A_log,
                           float* __restrict__ cumA,
                           float* __restrict__ hp)
{
    __shared__ float bc[32][68];   // 68 % 4 == 0 (16B rows), 68 % 32 == 4 (conflict-free reads)
    const int warp = threadIdx.x >> 5, lane = threadIdx.x & 31;
    const int d   = blockIdx.x * 8 + warp;
    const int seg = blockIdx.y;
    const int t0  = seg * SEG;

    const float A0 = -__expf(A_log[d * D_STATE + lane]);
    const float A1 = -__expf(A_log[d * D_STATE + lane + 32]);
    float h0 = 0.f, h1 = 0.f, p0 = 1.f, p1 = 1.f;

    for (int tc = t0; tc < t0 + SEG; tc += 32) {
        float dt_r = dtT[d * L_SEQ + tc + lane];
        float xc_r = xcT[d * L_SEQ + tc + lane];
        __syncthreads();
        #pragma unroll
        for (int i = 0; i < 2; i++) {      // 32 rows x 16 float4 = 512; 2/thread
            int e = threadIdx.x + i * 256;
            int r = e >> 4, c4 = e & 15;
            float4 v = *(const float4*)&dbl[(tc + r) * DBL_N + DT_RANK + c4 * 4];
            *(float4*)&bc[r][c4 * 4] = v;
        }
        __syncthreads();

        #pragma unroll
        for (int js = 0; js < 32; js += 8) {
            float dA0[8], dA1[8], dxb0[8], dxb1[8];
            #pragma unroll
            for (int j = 0; j < 8; j++) {
                float dt_t = __shfl_sync(0xffffffffu, dt_r, js + j);
                float x_t  = __shfl_sync(0xffffffffu, xc_r, js + j);
                dA0[j] = __expf(dt_t * A0);
                dA1[j] = __expf(dt_t * A1);
                float dx = dt_t * x_t;
                dxb0[j] = dx * bc[js + j][lane];
                dxb1[j] = dx * bc[js + j][lane + 32];
            }
            #pragma unroll
            for (int j = 0; j < 8; j++) {
                h0 = fmaf(dA0[j], h0, dxb0[j]);
                h1 = fmaf(dA1[j], h1, dxb1[j]);
                p0 *= dA0[j];
                p1 *= dA1[j];
            }
        }
    }
    const int base = (seg * D_INNER + d) * D_STATE;
    cumA[base + lane]      = p0;
    cumA[base + lane + 32] = p1;
    hp  [base + lane]      = h0;
    hp  [base + lane + 32] = h1;
}

// ---------------- chunked scan, combine ----------------
__global__ void scan_combine(const float* __restrict__ cumA,
                             const float* __restrict__ hp,
                             float* __restrict__ hinit)
{
    int idx = blockIdx.x * 256 + threadIdx.x;
    if (idx >= DN) return;
    float h = 0.f;
    #pragma unroll
    for (int s = 0; s < NSEG; s++) {
        hinit[s * DN + idx] = h;
        h = fmaf(cumA[s * DN + idx], h, hp[s * DN + idx]);
    }
}

// ---------------- chunked scan, pass 2 (float4 staging) ----------------
__global__ void scan_pass2(const float* __restrict__ dbl,
                           const float* __restrict__ dtT,
                           const float* __restrict__ xcT,
                           const float* __restrict__ zsT,
                           const float* __restrict__ A_log,
                           const float* __restrict__ D_skip,
                           const float* __restrict__ hinit,
                           float* __restrict__ y)
{
    __shared__ float bc[32][132];   // 132 % 4 == 0, 132 % 32 == 4
    const int warp = threadIdx.x >> 5, lane = threadIdx.x & 31;
    const int d   = blockIdx.x * 8 + warp;
    const int seg = blockIdx.y;
    const int t0  = seg * SEG;

    const float A0 = -__expf(A_log[d * D_STATE + lane]);
    const float A1 = -__expf(A_log[d * D_STATE + lane + 32]);
    const float Dd = D_skip[d];
    float h0 = hinit[seg * DN + d * D_STATE + lane];
    float h1 = hinit[seg * DN + d * D_STATE + lane + 32];

    for (int tc = t0; tc < t0 + SEG; tc += 32) {
        float dt_r = dtT[d * L_SEQ + tc + lane];
        float xc_r = xcT[d * L_SEQ + tc + lane];
        float zs_r = zsT[d * L_SEQ + tc + lane];
        __syncthreads();
        #pragma unroll
        for (int i = 0; i < 4; i++) {      // 32 rows x 32 float4 = 1024; 4/thread
            int e = threadIdx.x + i * 256;
            int r = e >> 5, c4 = e & 31;
            float4 v = *(const float4*)&dbl[(tc + r) * DBL_N + DT_RANK + c4 * 4];
            *(float4*)&bc[r][c4 * 4] = v;
        }
        __syncthreads();

        #pragma unroll
        for (int js = 0; js < 32; js += 8) {
            float dA0[8], dA1[8], dxb0[8], dxb1[8], cc0[8], cc1[8];
            #pragma unroll
            for (int j = 0; j < 8; j++) {
                float dt_t = __shfl_sync(0xffffffffu, dt_r, js + j);
                float x_t  = __shfl_sync(0xffffffffu, xc_r, js + j);
                dA0[j] = __expf(dt_t * A0);
                dA1[j] = __expf(dt_t * A1);
                float dx = dt_t * x_t;
                dxb0[j] = dx * bc[js + j][lane];
                dxb1[j] = dx * bc[js + j][lane + 32];
                cc0[j]  = bc[js + j][64 + lane];
                cc1[j]  = bc[js + j][96 + lane];
            }
            float ys[8];
            #pragma unroll
            for (int j = 0; j < 8; j++) {
                h0 = fmaf(dA0[j], h0, dxb0[j]);
                h1 = fmaf(dA1[j], h1, dxb1[j]);
                ys[j] = h0 * cc0[j] + h1 * cc1[j];
            }
            #pragma unroll
            for (int o = 16; o; o >>= 1) {
                #pragma unroll
                for (int j = 0; j < 8; j++)
                    ys[j] += __shfl_xor_sync(0xffffffffu, ys[j], o);
            }
            float x_l  = __shfl_sync(0xffffffffu, xc_r, js + (lane & 7));
            float zs_l = __shfl_sync(0xffffffffu, zs_r, js + (lane & 7));
            float yv = ys[0];
            #pragma unroll
            for (int j = 1; j < 8; j++)
                yv = (lane == j) ? ys[j] : yv;
            if (lane < 8) {
                int t = tc + js + lane;
                y[t * D_INNER + d] = to_tf32((yv + x_l * Dd) * zs_l);
            }
        }
    }
}

// ---------------- host launcher ----------------
static constexpr int smem_bytes(int BM, int BN, int BK, int NST) {
    return (BM * (BK + 4) + BK * (BN + 4)) * NST * 4;
}

extern "C" void kernel_launch(void* const* d_in, const int* in_sizes, int n_in,
                              void* d_out, int out_size)
{
    const float* x      = (const float*)d_in[0];
    const float* ln_g   = (const float*)d_in[1];
    const float* ln_b   = (const float*)d_in[2];
    const float* W_in   = (const float*)d_in[3];
    const float* conv_w = (const float*)d_in[4];
    const float* conv_b = (const float*)d_in[5];
    const float* W_x    = (const float*)d_in[6];
    const float* W_dt   = (const float*)d_in[7];
    const float* b_dt   = (const float*)d_in[8];
    const float* A_log  = (const float*)d_in[9];
    const float* D_skip = (const float*)d_in[10];
    const float* W_out  = (const float*)d_in[11];
    float* out = (float*)d_out;

    float *xn, *xz, *xc, *dbl, *dblr, *xcT, *dtT, *zsT, *y, *part;
    float *cumA, *hp, *hinit, *rWin, *rWx, *rWdt, *rWout;
    cudaGetSymbolAddress((void**)&xn,    g_xn);
    cudaGetSymbolAddress((void**)&xz,    g_xz);
    cudaGetSymbolAddress((void**)&xc,    g_xc);
    cudaGetSymbolAddress((void**)&dbl,   g_dbl);
    cudaGetSymbolAddress((void**)&dblr,  g_dblr);
    cudaGetSymbolAddress((void**)&xcT,   g_xcT);
    cudaGetSymbolAddress((void**)&dtT,   g_dtT);
    cudaGetSymbolAddress((void**)&zsT,   g_zsT);
    cudaGetSymbolAddress((void**)&y,     g_y);
    cudaGetSymbolAddress((void**)&part,  g_part);
    cudaGetSymbolAddress((void**)&cumA,  g_cumA);
    cudaGetSymbolAddress((void**)&hp,    g_hp);
    cudaGetSymbolAddress((void**)&hinit, g_hinit);
    cudaGetSymbolAddress((void**)&rWin,  g_rWin);
    cudaGetSymbolAddress((void**)&rWx,   g_rWx);
    cudaGetSymbolAddress((void**)&rWdt,  g_rWdt);
    cudaGetSymbolAddress((void**)&rWout, g_rWout);

    constexpr int SM_BIGN = smem_bytes(64, 128, 32, 2);  // 52224 -> 4 CTAs/SM
    constexpr int SM_SM3  = smem_bytes(64, 64, 32, 3);   // 53760 -> 4 CTAs/SM

    static bool attr_done = false;
    if (!attr_done) {
        cudaFuncSetAttribute(gemm_tf32<64,128,32,2>, cudaFuncAttributeMaxDynamicSharedMemorySize, SM_BIGN);
        cudaFuncSetAttribute(gemm_tf32<64,64,32,3>,  cudaFuncAttributeMaxDynamicSharedMemorySize, SM_SM3);
        attr_done = true;
    }

    // 0. pre-round weights to tf32
    round_weights<<<(N_WIN + N_WX + N_WDT + N_WOUT + 255) / 256, 256>>>(
        W_in, W_x, W_dt, W_out, rWin, rWx, rWdt, rWout);

    // 1. LayerNorm (rounded output)
    ln_kernel<<<L_SEQ, 256>>>(x, ln_g, ln_b, xn);

    // 2. in-projection: xz = xn @ W_in  (M=1024, N=3072, K=768) BN=128, 2-stage -> 384 CTAs
    gemm_tf32<64,128,32,2><<<dim3(2 * D_INNER / 128, L_SEQ / 64, 1), GEMM_THREADS, SM_BIGN>>>(
        xn, D_MODEL, rWin, 2 * D_INNER, nullptr, xz, 2 * D_INNER,
        L_SEQ, 2 * D_INNER, D_MODEL, D_MODEL, nullptr, 0, nullptr);

    // 3. conv+SiLU -> xc (rounded), xcT;  silu(z) -> zsT  (384 CTAs, 128-step tile)
    conv_fused_kernel<<<dim3(D_INNER / 32, L_SEQ / 128), dim3(32, 8)>>>(
        xz, conv_w, conv_b, xc, xcT, zsT);

    // 4. x-projection: dbl = xc @ W_x  (split-K=8, 3-stage) -> 384 CTAs; emits rounded dt_raw
    gemm_tf32<64,64,32,3><<<dim3(3, L_SEQ / 64, 8), GEMM_THREADS, SM_SM3>>>(
        xc, D_INNER, rWx, DBL_N, part, dbl, DBL_N,
        L_SEQ, DBL_N, D_INNER, D_INNER / 8, nullptr, 0, dblr);

    // 5. dtT = softplus(dt_raw @ W_dt + b_dt)^T (3-stage) -> 384 CTAs
    gemm_tf32<64,64,32,3><<<dim3(D_INNER / 64, L_SEQ / 64, 1), GEMM_THREADS, SM_SM3>>>(
        dblr, DT_RANK, rWdt, D_INNER, nullptr, dtT, L_SEQ,
        L_SEQ, D_INNER, DT_RANK, DT_RANK, b_dt, 1, nullptr);

    // 6-8. chunked selective scan
    scan_pass1<<<dim3(D_INNER / 8, NSEG), 256>>>(dbl, dtT, xcT, A_log, cumA, hp);
    scan_combine<<<(DN + 255) / 256, 256>>>(cumA, hp, hinit);
    scan_pass2<<<dim3(D_INNER / 8, NSEG), 256>>>(dbl, dtT, xcT, zsT, A_log, D_skip, hinit, y);

    // 9. out-projection: out = y @ W_out  (split-K=4, BN=128, 2-stage) -> 384 CTAs
    gemm_tf32<64,128,32,2><<<dim3(D_MODEL / 128, L_SEQ / 64, 4), GEMM_THREADS, SM_BIGN>>>(
        y, D_INNER, rWout, D_MODEL, part, out, D_MODEL,
        L_SEQ, D_MODEL, D_INNER, D_INNER / 4, nullptr, 0, nullptr);
}

// round 14
// speedup vs baseline: 1.0598x; 1.0014x over previous
#include <cstdint>
#include <cuda_runtime.h>
#include <cuda_bf16.h>
#include <mma.h>

using namespace nvcuda;

// ---------------- problem constants ----------------
#define L_SEQ   1024
#define D_MODEL 768
#define D_INNER 1536
#define D_STATE 64
#define D_CONV  4
#define DT_RANK 48
#define DBL_N   (DT_RANK + 2*D_STATE)   // 176
#define LN_EPS  1e-5f

#define GEMM_THREADS 256

// chunked scan
#define NSEG 8
#define SEG  (L_SEQ / NSEG)             // 128
#define DN   (D_INNER * D_STATE)        // 98304

// weight sizes
#define N_WIN  (D_MODEL * 2 * D_INNER)
#define N_WX   (D_INNER * DBL_N)
#define N_WDT  (DT_RANK * D_INNER)
#define N_WOUT (D_INNER * D_MODEL)

// ---------------- scratch (no allocations allowed) ----------------
__device__ float g_xn [L_SEQ * D_MODEL];
__device__ float g_xz [L_SEQ * 2 * D_INNER];
__device__ float g_xc [L_SEQ * D_INNER];
__device__ float g_dbl[L_SEQ * DBL_N];
__device__ float g_dblr[L_SEQ * DT_RANK];
__device__ float g_xcT[D_INNER * L_SEQ];
__device__ float g_dtT[D_INNER * L_SEQ];
__device__ float g_zsT[D_INNER * L_SEQ];
__device__ float g_y  [L_SEQ * D_INNER];
__device__ float g_part[8 * L_SEQ * DBL_N > 4 * L_SEQ * D_MODEL ?
                        8 * L_SEQ * DBL_N : 4 * L_SEQ * D_MODEL];
__device__ float g_cumA [NSEG * DN];
__device__ float g_hp   [NSEG * DN];
__device__ float g_hinit[NSEG * DN];
__device__ float g_rWin [N_WIN];
__device__ float g_rWx  [N_WX];
__device__ float g_rWdt [N_WDT];
__device__ float g_rWout[N_WOUT];
__device__ int   g_cnt[512];   // [0,256): GEMM split-K; [256,448): pass1 dblocks

// ---------------- helpers ----------------
__device__ __forceinline__ float to_tf32(float x) {
    float r;
    asm("cvt.rna.tf32.f32 %0, %1;" : "=f"(r) : "f"(x));
    return r;
}
__device__ __forceinline__ void cp_async16(void* smem_dst, const void* gmem_src) {
    unsigned int dst = (unsigned int)__cvta_generic_to_shared(smem_dst);
    asm volatile("cp.async.cg.shared.global [%0], [%1], 16;\n" :: "r"(dst), "l"(gmem_src));
}
__device__ __forceinline__ void cp_async_commit() {
    asm volatile("cp.async.commit_group;\n");
}
template<int N>
__device__ __forceinline__ void cp_async_wait() {
    asm volatile("cp.async.wait_group %0;\n" :: "n"(N));
}

// ---------------- weight pre-rounding to tf32 ----------------
__global__ void round_weights(const float* __restrict__ Win, const float* __restrict__ Wx,
                              const float* __restrict__ Wdt, const float* __restrict__ Wout,
                              float* __restrict__ rWin, float* __restrict__ rWx,
                              float* __restrict__ rWdt, float* __restrict__ rWout)
{
    int i = blockIdx.x * 256 + threadIdx.x;
    if (i < N_WIN) { rWin[i] = to_tf32(Win[i]); return; }
    i -= N_WIN;
    if (i < N_WX)  { rWx[i]  = to_tf32(Wx[i]);  return; }
    i -= N_WX;
    if (i < N_WDT) { rWdt[i] = to_tf32(Wdt[i]); return; }
    i -= N_WDT;
    if (i < N_WOUT) rWout[i] = to_tf32(Wout[i]);
}

// ---------------- LayerNorm (tf32-rounded output) ----------------
__global__ void ln_kernel(const float* __restrict__ x, const float* __restrict__ g,
                          const float* __restrict__ b, float* __restrict__ xn)
{
    int t = blockIdx.x;
    const float* xr = x + t * D_MODEL;
    float s = 0.f, s2 = 0.f;
    for (int i = threadIdx.x; i < D_MODEL; i += 256) {
        float v = xr[i];
        s += v; s2 += v * v;
    }
    #pragma unroll
    for (int o = 16; o; o >>= 1) {
        s  += __shfl_xor_sync(0xffffffffu, s,  o);
        s2 += __shfl_xor_sync(0xffffffffu, s2, o);
    }
    __shared__ float ss[8], ss2[8];
    __shared__ float mu_s, rstd_s;
    if ((threadIdx.x & 31) == 0) { ss[threadIdx.x >> 5] = s; ss2[threadIdx.x >> 5] = s2; }
    __syncthreads();
    if (threadIdx.x == 0) {
        float a = 0.f, a2 = 0.f;
        #pragma unroll
        for (int i = 0; i < 8; i++) { a += ss[i]; a2 += ss2[i]; }
        float mu = a / (float)D_MODEL;
        float var = a2 / (float)D_MODEL - mu * mu;
        mu_s = mu;
        rstd_s = rsqrtf(var + LN_EPS);
    }
    __syncthreads();
    float mu = mu_s, rstd = rstd_s;
    for (int i = threadIdx.x; i < D_MODEL; i += 256)
        xn[t * D_MODEL + i] = to_tf32((xr[i] - mu) * rstd * g[i] + b[i]);
}

// ---------------- tf32 WMMA GEMM: NST-stage cp.async pipeline, fused split-K reduce ----------------
template<int BM, int BN, int BK, int NST>
__global__ void __launch_bounds__(GEMM_THREADS)
gemm_tf32(const float* __restrict__ A, int lda,
          const float* __restrict__ B, int ldb,
          float* __restrict__ part, float* __restrict__ Cfinal, int ldc,
          int M, int N, int K, int Kslice,
          const float* __restrict__ bias, int epilogue,
          float* __restrict__ dtr)
{
    constexpr int ALD = BK + 4;
    constexpr int BLD = BN + 4;
    constexpr int CLD = BN + 4;
    constexpr int FM = BM / 4 / 16;
    constexpr int FN = BN / 2 / 16;
    constexpr int STAGE_F = BM*ALD + BK*BLD;

    extern __shared__ float smem[];

    const int tid  = threadIdx.x;
    const int warp = tid >> 5;
    const int wr   = warp >> 1;
    const int wc   = warp & 1;
    const int row_base = blockIdx.y * BM;
    const int col_base = blockIdx.x * BN;

    const int k_begin = blockIdx.z * Kslice;
    const int k_end   = min(K, k_begin + Kslice);

    const float4 zero4 = make_float4(0.f, 0.f, 0.f, 0.f);

    auto load_stage = [&](int s, int k0) {
        float* As = smem + s * STAGE_F;
        float* Bs = As + BM*ALD;
        #pragma unroll
        for (int i = 0; i < BM*BK/4/GEMM_THREADS; i++) {
            int idx = tid + i * GEMM_THREADS;
            int r = idx / (BK/4), ch = idx % (BK/4);
            int gc = k0 + ch * 4;
            float* dst = &As[r * ALD + ch * 4];
            if (gc + 4 <= k_end) cp_async16(dst, &A[(row_base + r) * (size_t)lda + gc]);
            else                 *(float4*)dst = zero4;
        }
        #pragma unroll
        for (int i = 0; i < BK*BN/4/GEMM_THREADS; i++) {
            int idx = tid + i * GEMM_THREADS;
            int r = idx / (BN/4), ch = idx % (BN/4);
            int gr = k0 + r, gc = col_base + ch * 4;
            float* dst = &Bs[r * BLD + ch * 4];
            if (gr < k_end && gc + 4 <= N) cp_async16(dst, &B[gr * (size_t)ldb + gc]);
            else                           *(float4*)dst = zero4;
        }
        cp_async_commit();
    };

    wmma::fragment<wmma::accumulator, 16, 16, 8, float> acc[FM][FN];
    #pragma unroll
    for (int i = 0; i < FM; i++)
        #pragma unroll
        for (int j = 0; j < FN; j++)
            wmma::fill_fragment(acc[i][j], 0.f);

    const int ntiles = (k_end - k_begin + BK - 1) / BK;
    #pragma unroll
    for (int p = 0; p < NST - 1; p++)
        if (p < ntiles) load_stage(p, k_begin + p * BK);

    for (int kt = 0; kt < ntiles; kt++) {
        int s = kt % NST;
        if (kt + NST - 1 < ntiles) {
            load_stage((kt + NST - 1) % NST, k_begin + (kt + NST - 1) * BK);
            cp_async_wait<NST - 1>();
        } else {
            cp_async_wait<0>();
        }
        __syncthreads();

        const float* Ac = smem + s * STAGE_F;
        const float* Bc = Ac + BM*ALD;
        #pragma unroll
        for (int kk = 0; kk < BK; kk += 8) {
            wmma::fragment<wmma::matrix_a, 16, 16, 8, wmma::precision::tf32, wmma::row_major> af[FM];
            wmma::fragment<wmma::matrix_b, 16, 16, 8, wmma::precision::tf32, wmma::row_major> bf[FN];
            #pragma unroll
            for (int i = 0; i < FM; i++)
                wmma::load_matrix_sync(af[i], &Ac[(wr * (BM/4) + i * 16) * ALD + kk], ALD);
            #pragma unroll
            for (int j = 0; j < FN; j++)
                wmma::load_matrix_sync(bf[j], &Bc[kk * BLD + wc * (BN/2) + j * 16], BLD);
            #pragma unroll
            for (int i = 0; i < FM; i++)
                #pragma unroll
                for (int j = 0; j < FN; j++)
                    wmma::mma_sync(acc[i][j], af[i], bf[j], acc[i][j]);
        }
        __syncthreads();
    }

    float* Cs = smem;
    #pragma unroll
    for (int i = 0; i < FM; i++)
        #pragma unroll
        for (int j = 0; j < FN; j++)
            wmma::store_matrix_sync(&Cs[(wr * (BM/4) + i * 16) * CLD + wc * (BN/2) + j * 16],
                                    acc[i][j], CLD, wmma::mem_row_major);
    __syncthreads();

    if (gridDim.z == 1) {
        if (epilogue == 1) {
            #pragma unroll
            for (int e = tid; e < BM * BN; e += GEMM_THREADS) {
                int tl = e % BM, dl = e / BM;
                int gr = row_base + tl, gc = col_base + dl;
                if (gr < M && gc < N) {
                    float v = Cs[tl * CLD + dl] + bias[gc];
                    v = fmaxf(v, 0.f) + log1pf(__expf(-fabsf(v)));
                    Cfinal[gc * (size_t)ldc + gr] = v;
                }
            }
        } else {
            #pragma unroll
            for (int e = tid; e < BM * BN; e += GEMM_THREADS) {
                int r = e / BN, c = e % BN;
                int gr = row_base + r, gc = col_base + c;
                if (gr < M && gc < N)
                    Cfinal[gr * (size_t)ldc + gc] = Cs[r * CLD + c];
            }
        }
        return;
    }

    // ---- fused split-K: write partial, last CTA reduces deterministically ----
    float* myp = part + (size_t)blockIdx.z * M * ldc;
    #pragma unroll
    for (int e = tid; e < BM * BN; e += GEMM_THREADS) {
        int r = e / BN, c = e % BN;
        int gr = row_base + r, gc = col_base + c;
        if (gr < M && gc < N)
            myp[gr * (size_t)ldc + gc] = Cs[r * CLD + c];
    }
    __threadfence();
    __syncthreads();

    __shared__ int is_last;
    const int tile = blockIdx.y * gridDim.x + blockIdx.x;
    if (tid == 0)
        is_last = (atomicAdd(&g_cnt[tile], 1) == (int)gridDim.z - 1);
    __syncthreads();
    if (!is_last) return;
    __threadfence();

    const int nz = gridDim.z;
    for (int e = tid; e < BM * BN; e += GEMM_THREADS) {
        int r = e / BN, c = e % BN;
        int gr = row_base + r, gc = col_base + c;
        if (gr < M && gc < N) {
            size_t off = gr * (size_t)ldc + gc;
            float v = 0.f;
            for (int z = 0; z < nz; z++)
                v += part[(size_t)z * M * ldc + off];
            Cfinal[off] = v;
            if (dtr && gc < DT_RANK)
                dtr[gr * DT_RANK + gc] = to_tf32(v);
        }
    }
    if (tid == 0) g_cnt[tile] = 0;
}

// ---------------- conv(d_conv=4)+SiLU -> xc (rounded), xcT  and  silu(z) -> zsT ----------------
// 512 threads (32x16): double the warps covering load latency; same 32ch x 128t tile.
__global__ void conv_fused_kernel(const float* __restrict__ xz,
                                  const float* __restrict__ conv_w,
                                  const float* __restrict__ conv_b,
                                  float* __restrict__ xc,
                                  float* __restrict__ xcT,
                                  float* __restrict__ zsT)
{
    __shared__ float xs[131][33];
    __shared__ float buf[128][33];
    const int tx = threadIdx.x, ty = threadIdx.y;
    const int d0 = blockIdx.x * 32;
    const int t0 = blockIdx.y * 128;
    const int d  = d0 + tx;

    for (int i = ty; i < 131; i += 16) {
        int t = t0 - 3 + i;
        xs[i][tx] = (t >= 0) ? xz[t * (2 * D_INNER) + d] : 0.f;
    }
    const float w0 = conv_w[d * D_CONV + 0];
    const float w1 = conv_w[d * D_CONV + 1];
    const float w2 = conv_w[d * D_CONV + 2];
    const float w3 = conv_w[d * D_CONV + 3];
    const float cb = conv_b[d];
    __syncthreads();

    for (int i = ty; i < 128; i += 16) {
        float acc = cb + xs[i][tx] * w0 + xs[i+1][tx] * w1 + xs[i+2][tx] * w2 + xs[i+3][tx] * w3;
        acc = acc * __frcp_rn(1.f + __expf(-acc));   // silu
        xc[(t0 + i) * D_INNER + d] = to_tf32(acc);
        buf[i][tx] = acc;
    }
    __syncthreads();
    #pragma unroll
    for (int jj = 0; jj < 4; jj++) {
        int t = tx + jj * 32;
        for (int i = ty; i < 32; i += 16)
            xcT[(d0 + i) * (size_t)L_SEQ + t0 + t] = buf[t][i];
    }
    __syncthreads();
    for (int i = ty; i < 128; i += 16) {
        float v = xz[(t0 + i) * (2 * D_INNER) + D_INNER + d];
        buf[i][tx] = v * __frcp_rn(1.f + __expf(-v));
    }
    __syncthreads();
    #pragma unroll
    for (int jj = 0; jj < 4; jj++) {
        int t = tx + jj * 32;
        for (int i = ty; i < 32; i += 16)
            zsT[(d0 + i) * (size_t)L_SEQ + t0 + t] = buf[t][i];
    }
}

// ---------------- chunked scan, pass 1 (float4 staging) + fused combine ----------------
__global__ void scan_pass1(const float* __restrict__ dbl,
                           const float* __restrict__ dtT,
                           const float* __restrict__ xcT,
                           const float* __restrict__ A_log,
                           float* __restrict__ cumA,
                           float* __restrict__ hp,
                           float* __restrict__ hinit)
{
    __shared__ float bc[32][68];
    const int warp = threadIdx.x >> 5, lane = threadIdx.x & 31;
    const int d   = blockIdx.x * 8 + warp;
    const int seg = blockIdx.y;
    const int t0  = seg * SEG;

    const float A0 = -__expf(A_log[d * D_STATE + lane]);
    const float A1 = -__expf(A_log[d * D_STATE + lane + 32]);
    float h0 = 0.f, h1 = 0.f, p0 = 1.f, p1 = 1.f;

    for (int tc = t0; tc < t0 + SEG; tc += 32) {
        float dt_r = dtT[d * L_SEQ + tc + lane];
        float xc_r = xcT[d * L_SEQ + tc + lane];
        __syncthreads();
        #pragma unroll
        for (int i = 0; i < 2; i++) {
            int e = threadIdx.x + i * 256;
            int r = e >> 4, c4 = e & 15;
            float4 v = *(const float4*)&dbl[(tc + r) * DBL_N + DT_RANK + c4 * 4];
            *(float4*)&bc[r][c4 * 4] = v;
        }
        __syncthreads();

        #pragma unroll
        for (int js = 0; js < 32; js += 8) {
            float dA0[8], dA1[8], dxb0[8], dxb1[8];
            #pragma unroll
            for (int j = 0; j < 8; j++) {
                float dt_t = __shfl_sync(0xffffffffu, dt_r, js + j);
                float x_t  = __shfl_sync(0xffffffffu, xc_r, js + j);
                dA0[j] = __expf(dt_t * A0);
                dA1[j] = __expf(dt_t * A1);
                float dx = dt_t * x_t;
                dxb0[j] = dx * bc[js + j][lane];
                dxb1[j] = dx * bc[js + j][lane + 32];
            }
            #pragma unroll
            for (int j = 0; j < 8; j++) {
                h0 = fmaf(dA0[j], h0, dxb0[j]);
                h1 = fmaf(dA1[j], h1, dxb1[j]);
                p0 *= dA0[j];
                p1 *= dA1[j];
            }
        }
    }
    const int base = (seg * D_INNER + d) * D_STATE;
    cumA[base + lane]      = p0;
    cumA[base + lane + 32] = p1;
    hp  [base + lane]      = h0;
    hp  [base + lane + 32] = h1;

    // ---- fused combine: last seg-CTA of this dblock builds hinit chains ----
    __threadfence();
    __syncthreads();
    __shared__ int is_last;
    if (threadIdx.x == 0)
        is_last = (atomicAdd(&g_cnt[256 + blockIdx.x], 1) == NSEG - 1);
    __syncthreads();
    if (!is_last) return;
    __threadfence();

    for (int e = threadIdx.x; e < 8 * D_STATE; e += 256) {
        int dl = e >> 6, n = e & 63;
        int off = (blockIdx.x * 8 + dl) * D_STATE + n;
        float h = 0.f;
        #pragma unroll
        for (int s = 0; s < NSEG; s++) {
            hinit[s * DN + off] = h;
            h = fmaf(cumA[s * DN + off], h, hp[s * DN + off]);
        }
    }
    if (threadIdx.x == 0) g_cnt[256 + blockIdx.x] = 0;
}

// ---------------- chunked scan, pass 2 (float4 staging) ----------------
__global__ void scan_pass2(const float* __restrict__ dbl,
                           const float* __restrict__ dtT,
                           const float* __restrict__ xcT,
                           const float* __restrict__ zsT,
                           const float* __restrict__ A_log,
                           const float* __restrict__ D_skip,
                           const float* __restrict__ hinit,
                           float* __restrict__ y)
{
    __shared__ float bc[32][132];
    const int warp = threadIdx.x >> 5, lane = threadIdx.x & 31;
    const int d   = blockIdx.x * 8 + warp;
    const int seg = blockIdx.y;
    const int t0  = seg * SEG;

    const float A0 = -__expf(A_log[d * D_STATE + lane]);
    const float A1 = -__expf(A_log[d * D_STATE + lane + 32]);
    const float Dd = D_skip[d];
    float h0 = hinit[seg * DN + d * D_STATE + lane];
    float h1 = hinit[seg * DN + d * D_STATE + lane + 32];

    for (int tc = t0; tc < t0 + SEG; tc += 32) {
        float dt_r = dtT[d * L_SEQ + tc + lane];
        float xc_r = xcT[d * L_SEQ + tc + lane];
        float zs_r = zsT[d * L_SEQ + tc + lane];
        __syncthreads();
        #pragma unroll
        for (int i = 0; i < 4; i++) {
            int e = threadIdx.x + i * 256;
            int r = e >> 5, c4 = e & 31;
            float4 v = *(const float4*)&dbl[(tc + r) * DBL_N + DT_RANK + c4 * 4];
            *(float4*)&bc[r][c4 * 4] = v;
        }
        __syncthreads();

        #pragma unroll
        for (int js = 0; js < 32; js += 8) {
            float dA0[8], dA1[8], dxb0[8], dxb1[8], cc0[8], cc1[8];
            #pragma unroll
            for (int j = 0; j < 8; j++) {
                float dt_t = __shfl_sync(0xffffffffu, dt_r, js + j);
                float x_t  = __shfl_sync(0xffffffffu, xc_r, js + j);
                dA0[j] = __expf(dt_t * A0);
                dA1[j] = __expf(dt_t * A1);
                float dx = dt_t * x_t;
                dxb0[j] = dx * bc[js + j][lane];
                dxb1[j] = dx * bc[js + j][lane + 32];
                cc0[j]  = bc[js + j][64 + lane];
                cc1[j]  = bc[js + j][96 + lane];
            }
            float ys[8];
            #pragma unroll
            for (int j = 0; j < 8; j++) {
                h0 = fmaf(dA0[j], h0, dxb0[j]);
                h1 = fmaf(dA1[j], h1, dxb1[j]);
                ys[j] = h0 * cc0[j] + h1 * cc1[j];
            }
            #pragma unroll
            for (int o = 16; o; o >>= 1) {
                #pragma unroll
                for (int j = 0; j < 8; j++)
                    ys[j] += __shfl_xor_sync(0xffffffffu, ys[j], o);
            }
            float x_l  = __shfl_sync(0xffffffffu, xc_r, js + (lane & 7));
            float zs_l = __shfl_sync(0xffffffffu, zs_r, js + (lane & 7));
            float yv = ys[0];
            #pragma unroll
            for (int j = 1; j < 8; j++)
                yv = (lane == j) ? ys[j] : yv;
            if (lane < 8) {
                int t = tc + js + lane;
                y[t * D_INNER + d] = to_tf32((yv + x_l * Dd) * zs_l);
            }
        }
    }
}

// ---------------- host launcher ----------------
static constexpr int smem_bytes(int BM, int BN, int BK, int NST) {
    return (BM * (BK + 4) + BK * (BN + 4)) * NST * 4;
}

extern "C" void kernel_launch(void* const* d_in, const int* in_sizes, int n_in,
                              void* d_out, int out_size)
{
    const float* x      = (const float*)d_in[0];
    const float* ln_g   = (const float*)d_in[1];
    const float* ln_b   = (const float*)d_in[2];
    const float* W_in   = (const float*)d_in[3];
    const float* conv_w = (const float*)d_in[4];
    const float* conv_b = (const float*)d_in[5];
    const float* W_x    = (const float*)d_in[6];
    const float* W_dt   = (const float*)d_in[7];
    const float* b_dt   = (const float*)d_in[8];
    const float* A_log  = (const float*)d_in[9];
    const float* D_skip = (const float*)d_in[10];
    const float* W_out  = (const float*)d_in[11];
    float* out = (float*)d_out;

    float *xn, *xz, *xc, *dbl, *dblr, *xcT, *dtT, *zsT, *y, *part;
    float *cumA, *hp, *hinit, *rWin, *rWx, *rWdt, *rWout;
    cudaGetSymbolAddress((void**)&xn,    g_xn);
    cudaGetSymbolAddress((void**)&xz,    g_xz);
    cudaGetSymbolAddress((void**)&xc,    g_xc);
    cudaGetSymbolAddress((void**)&dbl,   g_dbl);
    cudaGetSymbolAddress((void**)&dblr,  g_dblr);
    cudaGetSymbolAddress((void**)&xcT,   g_xcT);
    cudaGetSymbolAddress((void**)&dtT,   g_dtT);
    cudaGetSymbolAddress((void**)&zsT,   g_zsT);
    cudaGetSymbolAddress((void**)&y,     g_y);
    cudaGetSymbolAddress((void**)&part,  g_part);
    cudaGetSymbolAddress((void**)&cumA,  g_cumA);
    cudaGetSymbolAddress((void**)&hp,    g_hp);
    cudaGetSymbolAddress((void**)&hinit, g_hinit);
    cudaGetSymbolAddress((void**)&rWin,  g_rWin);
    cudaGetSymbolAddress((void**)&rWx,   g_rWx);
    cudaGetSymbolAddress((void**)&rWdt,  g_rWdt);
    cudaGetSymbolAddress((void**)&rWout, g_rWout);

    constexpr int SM_BIGN = smem_bytes(64, 128, 32, 2);  // 52224 -> 4 CTAs/SM
    constexpr int SM_SM3  = smem_bytes(64, 64, 32, 3);   // 53760 -> 4 CTAs/SM

    static bool attr_done = false;
    if (!attr_done) {
        cudaFuncSetAttribute(gemm_tf32<64,128,32,2>, cudaFuncAttributeMaxDynamicSharedMemorySize, SM_BIGN);
        cudaFuncSetAttribute(gemm_tf32<64,64,32,3>,  cudaFuncAttributeMaxDynamicSharedMemorySize, SM_SM3);
        attr_done = true;
    }

    // 0. pre-round weights to tf32
    round_weights<<<(N_WIN + N_WX + N_WDT + N_WOUT + 255) / 256, 256>>>(
        W_in, W_x, W_dt, W_out, rWin, rWx, rWdt, rWout);

    // 1. LayerNorm (rounded output)
    ln_kernel<<<L_SEQ, 256>>>(x, ln_g, ln_b, xn);

    // 2. in-projection: xz = xn @ W_in  (M=1024, N=3072, K=768) BN=128, 2-stage -> 384 CTAs
    gemm_tf32<64,128,32,2><<<dim3(2 * D_INNER / 128, L_SEQ / 64, 1), GEMM_THREADS, SM_BIGN>>>(
        xn, D_MODEL, rWin, 2 * D_INNER, nullptr, xz, 2 * D_INNER,
        L_SEQ, 2 * D_INNER, D_MODEL, D_MODEL, nullptr, 0, nullptr);

    // 3. conv+SiLU -> xc (rounded), xcT;  silu(z) -> zsT  (384 CTAs, 512 threads)
    conv_fused_kernel<<<dim3(D_INNER / 32, L_SEQ / 128), dim3(32, 16)>>>(
        xz, conv_w, conv_b, xc, xcT, zsT);

    // 4. x-projection: dbl = xc @ W_x  (split-K=8, 3-stage) -> 384 CTAs; emits rounded dt_raw
    gemm_tf32<64,64,32,3><<<dim3(3, L_SEQ / 64, 8), GEMM_THREADS, SM_SM3>>>(
        xc, D_INNER, rWx, DBL_N, part, dbl, DBL_N,
        L_SEQ, DBL_N, D_INNER, D_INNER / 8, nullptr, 0, dblr);

    // 5. dtT = softplus(dt_raw @ W_dt + b_dt)^T (3-stage) -> 384 CTAs
    gemm_tf32<64,64,32,3><<<dim3(D_INNER / 64, L_SEQ / 64, 1), GEMM_THREADS, SM_SM3>>>(
        dblr, DT_RANK, rWdt, D_INNER, nullptr, dtT, L_SEQ,
        L_SEQ, D_INNER, DT_RANK, DT_RANK, b_dt, 1, nullptr);

    // 6-7. chunked selective scan (combine fused into pass1)
    scan_pass1<<<dim3(D_INNER / 8, NSEG), 256>>>(dbl, dtT, xcT, A_log, cumA, hp, hinit);
    scan_pass2<<<dim3(D_INNER / 8, NSEG), 256>>>(dbl, dtT, xcT, zsT, A_log, D_skip, hinit, y);

    // 8. out-projection: out = y @ W_out  (split-K=4, BN=128, 2-stage) -> 384 CTAs
    gemm_tf32<64,128,32,2><<<dim3(D_MODEL / 128, L_SEQ / 64, 4), GEMM_THREADS, SM_BIGN>>>(
        y, D_INNER, rWout, D_MODEL, part, out, D_MODEL,
        L_SEQ, D_MODEL, D_INNER, D_INNER / 4, nullptr, 0, nullptr);
}